// round 5
// baseline (speedup 1.0000x reference)
#include <cuda_runtime.h>

// ---------------------------------------------------------------------------
// EnhancedQuanvolution: x(65536,1,28,28) -> 2x2 patches -> cumprod(cos)
// -> feat(784) @ W^T(784,10) + b -> log_softmax -> out(65536,10)
//
// Round 5: 2 images per thread (weight broadcast LDS amortized over both),
// warp-private double-buffered cp.async pipeline, no block barriers in the
// main loop. block=224 (7 warps, 64 imgs/warp), grid=147 (one wave).
// ---------------------------------------------------------------------------

__device__ __forceinline__ unsigned long long f32x2_fma(unsigned long long a,
                                                        unsigned long long b,
                                                        unsigned long long c) {
    unsigned long long d;
    asm("fma.rn.f32x2 %0, %1, %2, %3;" : "=l"(d) : "l"(a), "l"(b), "l"(c));
    return d;
}

__device__ __forceinline__ unsigned long long pack2(float lo, float hi) {
    unsigned long long d;
    asm("mov.b64 %0, {%1, %2};" : "=l"(d) : "f"(lo), "f"(hi));
    return d;
}

__device__ __forceinline__ void unpack2(unsigned long long v, float& lo, float& hi) {
    asm("mov.b64 {%0, %1}, %2;" : "=f"(lo), "=f"(hi) : "l"(v));
}

__device__ __forceinline__ void cp_async16(void* dst_smem, const void* src_gmem) {
    unsigned sd = (unsigned)__cvta_generic_to_shared(dst_smem);
    asm volatile("cp.async.cg.shared.global [%0], [%1], 16;"
                 :: "r"(sd), "l"(src_gmem) : "memory");
}

static constexpr int THREADS       = 224;   // 7 warps
static constexpr int WARPS         = 7;
static constexpr int IMG_PER_WARP  = 64;    // 2 per thread
static constexpr int IMG_PER_BLOCK = WARPS * IMG_PER_WARP;   // 448
static constexpr int NCHUNK        = 14;    // 14 patch-rows (2 image rows each)
static constexpr int PLANE_FLOATS  = IMG_PER_WARP * 28;          // 1792 (7168B)
static constexpr int SLOT_FLOATS   = 2 * PLANE_FLOATS;           // 3584 (14336B)
static constexpr int WARP_FLOATS   = 2 * SLOT_FLOATS;            // double buffer
static constexpr int STAGE_FLOATS  = WARPS * WARP_FLOATS;        // 50176 (200704B)
static constexpr int WS_U64        = 196 * 20;                   // 3920 (31360B)
static constexpr int SMEM_BYTES    = STAGE_FLOATS * 4 + WS_U64 * 8 + 40; // 232104

// Stage chunk c (image rows 2c,2c+1) for this warp's 64 images into slotbase.
__device__ __forceinline__ void stage_chunk(const float* __restrict__ x,
                                            float* __restrict__ slotbase,
                                            int gbase, int batch,
                                            int c, int lane) {
#pragma unroll
    for (int k = 0; k < 28; k++) {
        int n = lane + 32 * k;           // 0..895 = 64 imgs * 14 float4
        int img = n / 14;
        int j = n - img * 14;            // float4 index within 224B chunk
        int gimg = gbase + img;
        if (gimg < batch) {
            const float* src = x + (size_t)gimg * 784 + c * 56 + j * 4;
            float* dst = slotbase + ((j < 7) ? 0 : PLANE_FLOATS) + img * 28
                       + ((j < 7) ? j : (j - 7)) * 4;
            cp_async16(dst, src);
        }
    }
    asm volatile("cp.async.commit_group;" ::: "memory");
}

// cumprod-of-cos feature for a 2x2 patch -> two packed f32x2 values
__device__ __forceinline__ void patch_feat(float a, float b, float c, float d,
                                           unsigned long long& fA,
                                           unsigned long long& fB) {
    float f0 = __cosf(a);
    float f1 = f0 * __cosf(b);
    float f2 = f1 * __cosf(c);
    float f3 = f2 * __cosf(d);
    fA = pack2(f0, f1);
    fB = pack2(f2, f3);
}

__global__ __launch_bounds__(THREADS, 1)
void quanv_kernel(const float* __restrict__ x,
                  const float* __restrict__ W,
                  const float* __restrict__ bias,
                  float* __restrict__ out,
                  int batch) {
    extern __shared__ float sm[];
    unsigned long long* ws = (unsigned long long*)(sm + STAGE_FLOATS);
    float* bsh = (float*)(ws + WS_U64);

    const int tid  = threadIdx.x;
    const int lane = tid & 31;
    const int warp = tid >> 5;

    // ---- pack weights: per patch p, per output o:
    //      {W[o][4p+0],W[o][4p+1]}, {W[o][4p+2],W[o][4p+3]} -------------------
    for (int n = tid; n < WS_U64; n += THREADS) {
        int patch = n / 20;
        int t = n % 20;
        int o = t >> 1;
        int pr = t & 1;
        int f = patch * 4 + pr * 2;
        ws[n] = pack2(W[o * 784 + f], W[o * 784 + f + 1]);
    }
    if (tid < 10) bsh[tid] = bias[tid];
    __syncthreads();   // only block-wide barrier

    const int gbase = blockIdx.x * IMG_PER_BLOCK + warp * IMG_PER_WARP;
    float* wbuf = sm + warp * WARP_FLOATS;
    const int imgA = gbase + lane;          // thread's first image
    const int imgB = gbase + 32 + lane;     // thread's second image
    const bool okA = imgA < batch;
    const bool okB = imgB < batch;

    // ---- prologue: stage chunks 0,1 ------------------------------------------
    stage_chunk(x, wbuf, gbase, batch, 0, lane);
    stage_chunk(x, wbuf + SLOT_FLOATS, gbase, batch, 1, lane);

    unsigned long long accA[10], accB[10];
#pragma unroll
    for (int o = 0; o < 10; o++) { accA[o] = 0ULL; accB[o] = 0ULL; }

#pragma unroll 1
    for (int c = 0; c < NCHUNK; c++) {
        if (c < NCHUNK - 1) asm volatile("cp.async.wait_group 1;" ::: "memory");
        else                asm volatile("cp.async.wait_group 0;" ::: "memory");
        __syncwarp();

        float* slot = wbuf + (c & 1) * SLOT_FLOATS;
        const float4* p0a = (const float4*)(slot + lane * 28);                      // imgA row 2c
        const float4* p1a = (const float4*)(slot + PLANE_FLOATS + lane * 28);       // imgA row 2c+1
        const float4* p0b = (const float4*)(slot + (lane + 32) * 28);               // imgB row 2c
        const float4* p1b = (const float4*)(slot + PLANE_FLOATS + (lane + 32) * 28);// imgB row 2c+1

#pragma unroll
        for (int v = 0; v < 7; v++) {
            float4 q0a = p0a[v], q1a = p1a[v];
            float4 q0b = p0b[v], q1b = p1b[v];

            // ---- patch (c, 2v) ----
            {
                int patch = c * 14 + 2 * v;
                unsigned long long fAa, fBa, fAb, fBb;
                patch_feat(q0a.x, q0a.y, q1a.x, q1a.y, fAa, fBa);
                patch_feat(q0b.x, q0b.y, q1b.x, q1b.y, fAb, fBb);
                const ulonglong2* wp = (const ulonglong2*)&ws[patch * 20];
#pragma unroll
                for (int o = 0; o < 10; o++) {
                    ulonglong2 w = wp[o];
                    accA[o] = f32x2_fma(fAa, w.x, accA[o]);
                    accA[o] = f32x2_fma(fBa, w.y, accA[o]);
                    accB[o] = f32x2_fma(fAb, w.x, accB[o]);
                    accB[o] = f32x2_fma(fBb, w.y, accB[o]);
                }
            }
            // ---- patch (c, 2v+1) ----
            {
                int patch = c * 14 + 2 * v + 1;
                unsigned long long fAa, fBa, fAb, fBb;
                patch_feat(q0a.z, q0a.w, q1a.z, q1a.w, fAa, fBa);
                patch_feat(q0b.z, q0b.w, q1b.z, q1b.w, fAb, fBb);
                const ulonglong2* wp = (const ulonglong2*)&ws[patch * 20];
#pragma unroll
                for (int o = 0; o < 10; o++) {
                    ulonglong2 w = wp[o];
                    accA[o] = f32x2_fma(fAa, w.x, accA[o]);
                    accA[o] = f32x2_fma(fBa, w.y, accA[o]);
                    accB[o] = f32x2_fma(fAb, w.x, accB[o]);
                    accB[o] = f32x2_fma(fBb, w.y, accB[o]);
                }
            }
        }
        __syncwarp();

        if (c + 2 < NCHUNK) stage_chunk(x, slot, gbase, batch, c + 2, lane);
    }

    // ---- logits + log_softmax for both images ---------------------------------
#pragma unroll
    for (int half = 0; half < 2; half++) {
        const unsigned long long* acc = half ? accB : accA;
        int img = half ? imgB : imgA;
        bool ok = half ? okB : okA;
        if (!ok) continue;

        float lg[10];
        float m = -1e30f;
#pragma unroll
        for (int o = 0; o < 10; o++) {
            float lo, hi;
            unpack2(acc[o], lo, hi);
            lg[o] = lo + hi + bsh[o];
            m = fmaxf(m, lg[o]);
        }
        float s = 0.f;
#pragma unroll
        for (int o = 0; o < 10; o++) s += __expf(lg[o] - m);
        float lse = m + __logf(s);

        float* op = out + (size_t)img * 10;
#pragma unroll
        for (int o = 0; o < 10; o += 2) {
            *(float2*)(op + o) = make_float2(lg[o] - lse, lg[o + 1] - lse);
        }
    }
}

extern "C" void kernel_launch(void* const* d_in, const int* in_sizes, int n_in,
                              void* d_out, int out_size) {
    const float* x = (const float*)d_in[0];   // (B,1,28,28) fp32
    const float* W = (const float*)d_in[1];   // (10,784)    fp32
    const float* b = (const float*)d_in[2];   // (10,)       fp32
    float* out = (float*)d_out;               // (B,10)      fp32

    int batch = in_sizes[0] / 784;
    int grid = (batch + IMG_PER_BLOCK - 1) / IMG_PER_BLOCK;

    cudaFuncSetAttribute(quanv_kernel,
                         cudaFuncAttributeMaxDynamicSharedMemorySize, SMEM_BYTES);
    quanv_kernel<<<grid, THREADS, SMEM_BYTES>>>(x, W, b, out, batch);
}

// round 6
// speedup vs baseline: 1.4581x; 1.4581x over previous
#include <cuda_runtime.h>

// ---------------------------------------------------------------------------
// EnhancedQuanvolution: x(65536,1,28,28) -> 2x2 patches -> cumprod(cos)
// -> feat(784) @ W^T(784,10) + b -> log_softmax -> out(65536,10)
//
// Round 6: 2 images/thread with OUTPUT-PACKED accumulators:
//   acc[op] = {logit_{2op}, logit_{2op+1}} (f32x2), 5 u64 accs per image.
// Weights re-laid in smem as ws[patch][op_pair][k] = {W[2op][4p+k],W[2op+1][4p+k]}
// so each patch needs 10 broadcast LDS.128 shared by both images.
// Warp-private double-buffered cp.async pipeline, no block barriers in loop.
// block=224 (7 warps, 64 imgs/warp), grid=147.
// ---------------------------------------------------------------------------

__device__ __forceinline__ unsigned long long f32x2_fma(unsigned long long a,
                                                        unsigned long long b,
                                                        unsigned long long c) {
    unsigned long long d;
    asm("fma.rn.f32x2 %0, %1, %2, %3;" : "=l"(d) : "l"(a), "l"(b), "l"(c));
    return d;
}

__device__ __forceinline__ unsigned long long pack2(float lo, float hi) {
    unsigned long long d;
    asm("mov.b64 %0, {%1, %2};" : "=l"(d) : "f"(lo), "f"(hi));
    return d;
}

__device__ __forceinline__ void unpack2(unsigned long long v, float& lo, float& hi) {
    asm("mov.b64 {%0, %1}, %2;" : "=f"(lo), "=f"(hi) : "l"(v));
}

__device__ __forceinline__ void cp_async16(void* dst_smem, const void* src_gmem) {
    unsigned sd = (unsigned)__cvta_generic_to_shared(dst_smem);
    asm volatile("cp.async.cg.shared.global [%0], [%1], 16;"
                 :: "r"(sd), "l"(src_gmem) : "memory");
}

static constexpr int THREADS       = 224;   // 7 warps
static constexpr int WARPS         = 7;
static constexpr int IMG_PER_WARP  = 64;    // 2 per thread
static constexpr int IMG_PER_BLOCK = WARPS * IMG_PER_WARP;       // 448
static constexpr int NCHUNK        = 14;
static constexpr int PLANE_FLOATS  = IMG_PER_WARP * 28;          // 1792 (7168B)
static constexpr int SLOT_FLOATS   = 2 * PLANE_FLOATS;           // 3584 (14336B)
static constexpr int WARP_FLOATS   = 2 * SLOT_FLOATS;
static constexpr int STAGE_FLOATS  = WARPS * WARP_FLOATS;        // 50176 (200704B)
static constexpr int WS_U64        = 196 * 20;                   // 3920 (31360B)
static constexpr int SMEM_BYTES    = STAGE_FLOATS * 4 + WS_U64 * 8 + 40; // 232104

// Stage chunk c (image rows 2c,2c+1) for this warp's 64 images into slotbase.
__device__ __forceinline__ void stage_chunk(const float* __restrict__ x,
                                            float* __restrict__ slotbase,
                                            int gbase, int batch,
                                            int c, int lane) {
#pragma unroll
    for (int k = 0; k < 28; k++) {
        int n = lane + 32 * k;           // 0..895 = 64 imgs * 14 float4
        int img = n / 14;
        int j = n - img * 14;
        int gimg = gbase + img;
        if (gimg < batch) {
            const float* src = x + (size_t)gimg * 784 + c * 56 + j * 4;
            float* dst = slotbase + ((j < 7) ? 0 : PLANE_FLOATS) + img * 28
                       + ((j < 7) ? j : (j - 7)) * 4;
            cp_async16(dst, src);
        }
    }
    asm volatile("cp.async.commit_group;" ::: "memory");
}

// cumprod-of-cos feature, duplicated into f32x2 lanes: d_k = {f_k, f_k}
__device__ __forceinline__ void patch_feat_dup(float a, float b, float c, float d,
                                               unsigned long long* dup) {
    float f0 = __cosf(a);
    float f1 = f0 * __cosf(b);
    float f2 = f1 * __cosf(c);
    float f3 = f2 * __cosf(d);
    dup[0] = pack2(f0, f0);
    dup[1] = pack2(f1, f1);
    dup[2] = pack2(f2, f2);
    dup[3] = pack2(f3, f3);
}

__global__ __launch_bounds__(THREADS, 1)
void quanv_kernel(const float* __restrict__ x,
                  const float* __restrict__ W,
                  const float* __restrict__ bias,
                  float* __restrict__ out,
                  int batch) {
    extern __shared__ float sm[];
    unsigned long long* ws = (unsigned long long*)(sm + STAGE_FLOATS);
    float* bsh = (float*)(ws + WS_U64);

    const int tid  = threadIdx.x;
    const int lane = tid & 31;
    const int warp = tid >> 5;

    // ---- pack weights: ws[p*20 + op*4 + k] = {W[2op][4p+k], W[2op+1][4p+k]} --
    for (int n = tid; n < WS_U64; n += THREADS) {
        int patch = n / 20;
        int t = n % 20;
        int op = t >> 2;          // output pair 0..4
        int k = t & 3;            // feature index within patch
        int f = patch * 4 + k;
        ws[n] = pack2(W[(2 * op) * 784 + f], W[(2 * op + 1) * 784 + f]);
    }
    if (tid < 10) bsh[tid] = bias[tid];
    __syncthreads();   // only block-wide barrier

    const int gbase = blockIdx.x * IMG_PER_BLOCK + warp * IMG_PER_WARP;
    float* wbuf = sm + warp * WARP_FLOATS;
    const int imgA = gbase + lane;
    const int imgB = gbase + 32 + lane;

    // ---- prologue: stage chunks 0,1 ------------------------------------------
    stage_chunk(x, wbuf, gbase, batch, 0, lane);
    stage_chunk(x, wbuf + SLOT_FLOATS, gbase, batch, 1, lane);

    unsigned long long accA[5], accB[5];
#pragma unroll
    for (int op = 0; op < 5; op++) { accA[op] = 0ULL; accB[op] = 0ULL; }

#pragma unroll 1
    for (int c = 0; c < NCHUNK; c++) {
        if (c < NCHUNK - 1) asm volatile("cp.async.wait_group 1;" ::: "memory");
        else                asm volatile("cp.async.wait_group 0;" ::: "memory");
        __syncwarp();

        float* slot = wbuf + (c & 1) * SLOT_FLOATS;
        const float4* p0a = (const float4*)(slot + lane * 28);
        const float4* p1a = (const float4*)(slot + PLANE_FLOATS + lane * 28);
        const float4* p0b = (const float4*)(slot + (lane + 32) * 28);
        const float4* p1b = (const float4*)(slot + PLANE_FLOATS + (lane + 32) * 28);

#pragma unroll 1
        for (int v = 0; v < 7; v++) {
            float4 q0a = p0a[v], q1a = p1a[v];
            float4 q0b = p0b[v], q1b = p1b[v];
            const ulonglong2* wp = (const ulonglong2*)&ws[(c * 14 + 2 * v) * 20];

            // ---- patch (c, 2v): x/y halves ----
            {
                unsigned long long dA[4], dB[4];
                patch_feat_dup(q0a.x, q0a.y, q1a.x, q1a.y, dA);
                patch_feat_dup(q0b.x, q0b.y, q1b.x, q1b.y, dB);
#pragma unroll
                for (int op = 0; op < 5; op++) {
                    ulonglong2 w01 = wp[op * 2];       // k0,k1
                    ulonglong2 w23 = wp[op * 2 + 1];   // k2,k3
                    accA[op] = f32x2_fma(dA[0], w01.x, accA[op]);
                    accA[op] = f32x2_fma(dA[1], w01.y, accA[op]);
                    accA[op] = f32x2_fma(dA[2], w23.x, accA[op]);
                    accA[op] = f32x2_fma(dA[3], w23.y, accA[op]);
                    accB[op] = f32x2_fma(dB[0], w01.x, accB[op]);
                    accB[op] = f32x2_fma(dB[1], w01.y, accB[op]);
                    accB[op] = f32x2_fma(dB[2], w23.x, accB[op]);
                    accB[op] = f32x2_fma(dB[3], w23.y, accB[op]);
                }
            }
            // ---- patch (c, 2v+1): z/w halves ----
            {
                unsigned long long dA[4], dB[4];
                patch_feat_dup(q0a.z, q0a.w, q1a.z, q1a.w, dA);
                patch_feat_dup(q0b.z, q0b.w, q1b.z, q1b.w, dB);
                const ulonglong2* wq = wp + 10;        // next patch's 20 u64
#pragma unroll
                for (int op = 0; op < 5; op++) {
                    ulonglong2 w01 = wq[op * 2];
                    ulonglong2 w23 = wq[op * 2 + 1];
                    accA[op] = f32x2_fma(dA[0], w01.x, accA[op]);
                    accA[op] = f32x2_fma(dA[1], w01.y, accA[op]);
                    accA[op] = f32x2_fma(dA[2], w23.x, accA[op]);
                    accA[op] = f32x2_fma(dA[3], w23.y, accA[op]);
                    accB[op] = f32x2_fma(dB[0], w01.x, accB[op]);
                    accB[op] = f32x2_fma(dB[1], w01.y, accB[op]);
                    accB[op] = f32x2_fma(dB[2], w23.x, accB[op]);
                    accB[op] = f32x2_fma(dB[3], w23.y, accB[op]);
                }
            }
        }
        __syncwarp();

        if (c + 2 < NCHUNK) stage_chunk(x, slot, gbase, batch, c + 2, lane);
    }

    // ---- logits + log_softmax for both images ---------------------------------
#pragma unroll 1
    for (int half = 0; half < 2; half++) {
        const unsigned long long* acc = half ? accB : accA;
        int img = half ? imgB : imgA;
        if (img >= batch) continue;

        float lg[10];
        float m = -1e30f;
#pragma unroll
        for (int op = 0; op < 5; op++) {
            float lo, hi;
            unpack2(acc[op], lo, hi);
            lg[2 * op]     = lo + bsh[2 * op];
            lg[2 * op + 1] = hi + bsh[2 * op + 1];
            m = fmaxf(m, fmaxf(lg[2 * op], lg[2 * op + 1]));
        }
        float s = 0.f;
#pragma unroll
        for (int o = 0; o < 10; o++) s += __expf(lg[o] - m);
        float lse = m + __logf(s);

        float* op_ = out + (size_t)img * 10;
#pragma unroll
        for (int o = 0; o < 10; o += 2) {
            *(float2*)(op_ + o) = make_float2(lg[o] - lse, lg[o + 1] - lse);
        }
    }
}

extern "C" void kernel_launch(void* const* d_in, const int* in_sizes, int n_in,
                              void* d_out, int out_size) {
    const float* x = (const float*)d_in[0];   // (B,1,28,28) fp32
    const float* W = (const float*)d_in[1];   // (10,784)    fp32
    const float* b = (const float*)d_in[2];   // (10,)       fp32
    float* out = (float*)d_out;               // (B,10)      fp32

    int batch = in_sizes[0] / 784;
    int grid = (batch + IMG_PER_BLOCK - 1) / IMG_PER_BLOCK;

    cudaFuncSetAttribute(quanv_kernel,
                         cudaFuncAttributeMaxDynamicSharedMemorySize, SMEM_BYTES);
    quanv_kernel<<<grid, THREADS, SMEM_BYTES>>>(x, W, b, out, batch);
}